// round 12
// baseline (speedup 1.0000x reference)
#include <cuda_runtime.h>
#include <cuda_fp16.h>
#include <cstdint>

// hashNerf on sm_103 (plain target), R12: chunked two-stream pipeline.
// encode chunk i (default stream)  --event-->  mlp chunk i (stream s2)
// so MLP of chunk i overlaps encode of chunk i+1 inside the captured graph.
// Kernels are the proven R8 forms (encode direct-__ldg + inline prep; MLP
// 32 pts/warp HMMA, TILES=4, natural regs).

#define LVL   16
#define TSZ   262144
#define TMASK 0x3FFFFu
#define N_PTS_MAX 1048576
#define TILES 4
#define NCHUNK 4
#define N_TAB {16.f,21.f,27.f,36.f,48.f,64.f,84.f,111.f,147.f,194.f,256.f,337.f,445.f,588.f,776.f,1024.f}

#define WPAD 72          // weight row stride in halves (144B -> conflict-free ldmatrix)
#define FPAD 40          // feature row stride in halves (80B, 16B-aligned rows)
#define OFF_W1 0
#define OFF_W2 2304      // 32*72
#define OFF_W3 6912      // 2304 + 64*72
#define OFF_W4 11520     // 6912 + 64*72
#define IMG_HALVES 12032 // + 64*8
#define PREP_BLOCKS 47   // ceil(12032/256)

__device__ __align__(16) unsigned short g_prepW[IMG_HALVES];
__device__ uint4 g_feat[N_PTS_MAX * 4];   // 32 f16 per point = 4 uint4

// ---------- helpers ----------
__device__ __forceinline__ uint32_t smem_u32(const void* p) {
    uint32_t a;
    asm("{ .reg .u64 t; cvta.to.shared.u64 t, %1; cvt.u32.u64 %0, t; }" : "=r"(a) : "l"(p));
    return a;
}
__device__ __forceinline__ uint32_t pack_h2(float lo, float hi) {
    uint32_t r;
    asm("cvt.rn.f16x2.f32 %0, %1, %2;" : "=r"(r) : "f"(hi), "f"(lo));
    return r;
}
__device__ __forceinline__ void ldsm_x4(uint32_t& r0, uint32_t& r1, uint32_t& r2, uint32_t& r3, uint32_t addr) {
    asm volatile("ldmatrix.sync.aligned.m8n8.x4.shared.b16 {%0,%1,%2,%3}, [%4];"
                 : "=r"(r0), "=r"(r1), "=r"(r2), "=r"(r3) : "r"(addr));
}
__device__ __forceinline__ void ldsm_x4_t(uint32_t& r0, uint32_t& r1, uint32_t& r2, uint32_t& r3, uint32_t addr) {
    asm volatile("ldmatrix.sync.aligned.m8n8.x4.trans.shared.b16 {%0,%1,%2,%3}, [%4];"
                 : "=r"(r0), "=r"(r1), "=r"(r2), "=r"(r3) : "r"(addr));
}
__device__ __forceinline__ void ldsm_x2_t(uint32_t& r0, uint32_t& r1, uint32_t addr) {
    asm volatile("ldmatrix.sync.aligned.m8n8.x2.trans.shared.b16 {%0,%1}, [%2];"
                 : "=r"(r0), "=r"(r1) : "r"(addr));
}
__device__ __forceinline__ void mma16816(float* c, const uint32_t* a, uint32_t b0, uint32_t b1) {
    asm volatile("mma.sync.aligned.m16n8k16.row.col.f32.f16.f16.f32 "
                 "{%0,%1,%2,%3}, {%4,%5,%6,%7}, {%8,%9}, {%0,%1,%2,%3};"
                 : "+f"(c[0]), "+f"(c[1]), "+f"(c[2]), "+f"(c[3])
                 : "r"(a[0]), "r"(a[1]), "r"(a[2]), "r"(a[3]), "r"(b0), "r"(b1));
}
__device__ __forceinline__ float lrelu(float v) { return (v >= 0.f) ? v : 0.01f * v; }

// ---------- K1: hash encode (+ inline weight prep on first 47 blocks of chunk 0) ----------
__global__ void __launch_bounds__(256)
encode_kernel(const float* __restrict__ X, const float* __restrict__ tab,
              const float* __restrict__ W1, const float* __restrict__ W2,
              const float* __restrict__ W3, const float* __restrict__ W4,
              int base, int n) {
    const int tid = threadIdx.x;

    if (base == 0 && blockIdx.x < PREP_BLOCKS) {
        int idx = blockIdx.x * 256 + tid;
        if (idx < IMG_HALVES) {
            float v = 0.f;
            if (idx < OFF_W2) {
                int k = idx / WPAD, c = idx % WPAD;
                if (c < 64) v = W1[k * 64 + c];
            } else if (idx < OFF_W3) {
                int j = idx - OFF_W2, k = j / WPAD, c = j % WPAD;
                if (c < 64) v = W2[k * 64 + c];
            } else if (idx < OFF_W4) {
                int j = idx - OFF_W3, k = j / WPAD, c = j % WPAD;
                if (c < 64) v = W3[k * 64 + c];
            } else {
                int j = idx - OFF_W4, k = j >> 3, c = j & 7;
                if (c < 3) v = W4[k * 3 + c];
            }
            unsigned short hv;
            asm("{ .reg .b16 t; cvt.rn.f16.f32 t, %1; mov.b16 %0, t; }" : "=h"(hv) : "f"(v));
            g_prepW[idx] = hv;
        }
    }

    const int pt = base + blockIdx.x * 256 + tid;
    if (pt >= n) return;
    const float Ntab[16] = N_TAB;
    const float2 xy = __ldg((const float2*)X + pt);
    const float x = xy.x, y = xy.y;

    uint32_t packed[16];
#pragma unroll
    for (int l = 0; l < LVL; l++) {
        float xs = x * Ntab[l], ys = y * Ntab[l];
        float xf = floorf(xs), yf = floorf(ys);
        unsigned xi = (unsigned)xf, yi = (unsigned)yf;
        unsigned hy = (yi * 2654435761u) & TMASK;
        unsigned hx = xi;                 // < 2^18 already
        unsigned hxy = hx ^ hy;
        const float2* tl = (const float2*)tab + (size_t)l * TSZ;
        float2 v0 = __ldg(tl);
        float2 v1 = __ldg(tl + hy);
        float2 v2 = __ldg(tl + hx);
        float2 v3 = __ldg(tl + hxy);
        float fx = xs - xf, fy = ys - yf;
        float cx = 1.f - fx, cy = 1.f - fy;
        float w0 = cx * cy, w1 = cx * fy, w2 = fx * cy, w3 = fx * fy;
        float f0 = w0 * v0.x + w1 * v1.x + w2 * v2.x + w3 * v3.x;
        float f1 = w0 * v0.y + w1 * v1.y + w2 * v2.y + w3 * v3.y;
        packed[l] = pack_h2(f0, f1);
    }
    uint4* dst = g_feat + (size_t)pt * 4;
#pragma unroll
    for (int i = 0; i < 4; i++)
        dst[i] = make_uint4(packed[4 * i], packed[4 * i + 1], packed[4 * i + 2], packed[4 * i + 3]);
}

// ---------- K2: MLP (32 pts/warp, R8 structure) ----------
__global__ void __launch_bounds__(128)
mlp_kernel(const float* __restrict__ b1, const float* __restrict__ b2,
           const float* __restrict__ b3, const float* __restrict__ b4,
           float* __restrict__ out, int base, int n) {
    __shared__ __align__(16) unsigned short sW[IMG_HALVES];      // 24064 B
    __shared__ __align__(16) unsigned short sF[4][32 * FPAD];    // 10240 B
    __shared__ float sb[3][64];
    __shared__ float sb4[8];

    const int tid  = threadIdx.x;
    const int warp = tid >> 5;
    const int lane = tid & 31;

    {
        const uint4* src = (const uint4*)g_prepW;
        uint4* dst = (uint4*)sW;
        for (int i = tid; i < IMG_HALVES / 8; i += 128) dst[i] = src[i];
    }
    if (tid < 64) { sb[0][tid] = b1[tid]; sb[1][tid] = b2[tid]; sb[2][tid] = b3[tid]; }
    if (tid < 8) sb4[tid] = (tid < 3) ? b4[tid] : 0.f;
    __syncthreads();

    const uint32_t uW = smem_u32(sW);
    const uint32_t uF = smem_u32(sF[warp]);
    const int l15 = lane & 15;
    const int lhi = (lane >> 4) << 3;       // +8 halves for upper half-warp
    const int tg2 = (lane & 3) << 1;        // accumulator column pair base
    const int g   = lane >> 2;              // accumulator row base

#pragma unroll 1
    for (int it = 0; it < TILES; it++) {
        const int pbase = base + (blockIdx.x * TILES + it) * 128 + warp * 32;
        if (pbase >= n) break;

        // stage this warp's 32 feature rows (coalesced uint4 copy into FPAD rows)
        __syncwarp();   // it>0: prior ldsm reads complete before overwrite
        {
            const uint4* src = g_feat + (size_t)pbase * 4;   // 128 uint4
            unsigned short* dstbase = sF[warp];
#pragma unroll
            for (int i = 0; i < 4; i++) {
                int j = lane + 32 * i;                        // 0..127
                uint4 v = src[j];                             // point j>>2, slot j&3
                *(uint4*)(dstbase + (j >> 2) * FPAD + (j & 3) * 8) = v;
            }
        }
        __syncwarp();

        // A fragments: a[mtile][ktile][4]
        uint32_t a[2][4][4];
#pragma unroll
        for (int mt = 0; mt < 2; mt++)
#pragma unroll
            for (int kt = 0; kt < 2; kt++) {
                uint32_t ad = uF + (uint32_t)(((mt * 16 + l15) * FPAD + kt * 16 + lhi) * 2);
                ldsm_x4(a[mt][kt][0], a[mt][kt][1], a[mt][kt][2], a[mt][kt][3], ad);
            }

        const uint32_t woffs[3] = {OFF_W1 * 2u, OFF_W2 * 2u, OFF_W3 * 2u};
        const int nkts[3] = {2, 4, 4};

#pragma unroll 1
        for (int layer = 0; layer < 3; layer++) {
            const uint32_t wb = uW + woffs[layer];
            const int nkt = nkts[layer];
            float c[2][8][4];
#pragma unroll
            for (int mt = 0; mt < 2; mt++)
#pragma unroll
                for (int nt = 0; nt < 8; nt++) {
                    float v0 = sb[layer][8 * nt + tg2];
                    float v1 = sb[layer][8 * nt + tg2 + 1];
                    c[mt][nt][0] = v0; c[mt][nt][1] = v1;
                    c[mt][nt][2] = v0; c[mt][nt][3] = v1;
                }
#pragma unroll
            for (int kt = 0; kt < 4; kt++) {
                if (kt >= nkt) break;
#pragma unroll
                for (int n2 = 0; n2 < 4; n2++) {
                    uint32_t b0, b1, b2, b3;
                    uint32_t bd = wb + (uint32_t)(((kt * 16 + l15) * WPAD + n2 * 16 + lhi) * 2);
                    ldsm_x4_t(b0, b1, b2, b3, bd);
#pragma unroll
                    for (int mt = 0; mt < 2; mt++) {
                        mma16816(c[mt][2 * n2],     a[mt][kt], b0, b1);
                        mma16816(c[mt][2 * n2 + 1], a[mt][kt], b2, b3);
                    }
                }
            }
            // leaky-relu + repack accumulators as next-layer A fragments
#pragma unroll
            for (int mt = 0; mt < 2; mt++)
#pragma unroll
                for (int j = 0; j < 4; j++) {
                    a[mt][j][0] = pack_h2(lrelu(c[mt][2 * j][0]),     lrelu(c[mt][2 * j][1]));
                    a[mt][j][1] = pack_h2(lrelu(c[mt][2 * j][2]),     lrelu(c[mt][2 * j][3]));
                    a[mt][j][2] = pack_h2(lrelu(c[mt][2 * j + 1][0]), lrelu(c[mt][2 * j + 1][1]));
                    a[mt][j][3] = pack_h2(lrelu(c[mt][2 * j + 1][2]), lrelu(c[mt][2 * j + 1][3]));
                }
        }

        // ---- layer 4: 64 -> 3 (single n8 tile, cols 3..7 zero-padded) ----
        float c4[2][4];
#pragma unroll
        for (int mt = 0; mt < 2; mt++) {
            c4[mt][0] = sb4[tg2]; c4[mt][1] = sb4[tg2 + 1];
            c4[mt][2] = sb4[tg2]; c4[mt][3] = sb4[tg2 + 1];
        }
#pragma unroll
        for (int kt = 0; kt < 4; kt++) {
            uint32_t b0, b1;
            uint32_t bd = uW + OFF_W4 * 2u + (uint32_t)(((kt * 16 + l15) * 8) * 2);
            ldsm_x2_t(b0, b1, bd);
#pragma unroll
            for (int mt = 0; mt < 2; mt++) mma16816(c4[mt], a[mt][kt], b0, b1);
        }

        // relu + predicated stores: rows (g, g+8) per m-tile, cols (tg2, tg2+1)
#pragma unroll
        for (int mt = 0; mt < 2; mt++) {
            int p0 = pbase + mt * 16 + g;
            int p1 = p0 + 8;
            float v0 = fmaxf(c4[mt][0], 0.f), v1 = fmaxf(c4[mt][1], 0.f);
            float v2 = fmaxf(c4[mt][2], 0.f), v3 = fmaxf(c4[mt][3], 0.f);
            if (tg2 < 3) {
                if (p0 < n) out[3 * p0 + tg2] = v0;
                if (p1 < n) out[3 * p1 + tg2] = v2;
            }
            if (tg2 + 1 < 3) {
                if (p0 < n) out[3 * p0 + tg2 + 1] = v1;
                if (p1 < n) out[3 * p1 + tg2 + 1] = v3;
            }
        }
    }
}

extern "C" void kernel_launch(void* const* d_in, const int* in_sizes, int n_in,
                              void* d_out, int out_size) {
    const float* X   = (const float*)d_in[0];
    const float* tab = (const float*)d_in[1];
    const float* W1  = (const float*)d_in[2];
    const float* b1  = (const float*)d_in[3];
    const float* W2  = (const float*)d_in[4];
    const float* b2  = (const float*)d_in[5];
    const float* W3  = (const float*)d_in[6];
    const float* b3  = (const float*)d_in[7];
    const float* W4  = (const float*)d_in[8];
    const float* b4  = (const float*)d_in[9];
    float* out = (float*)d_out;

    int n = in_sizes[0] / 2;

    // Fork a second stream inside the (captured) default stream: encode chunks
    // stay on the default stream; each MLP chunk runs on s2 gated by an event
    // recorded after its encode chunk. Host-side handles only (no device mem);
    // intentionally not destroyed (kernel_launch is called a handful of times).
    cudaStream_t s2;
    cudaStreamCreateWithFlags(&s2, cudaStreamNonBlocking);
    cudaEvent_t evc[NCHUNK], evj;
    for (int i = 0; i < NCHUNK; i++) cudaEventCreateWithFlags(&evc[i], cudaEventDisableTiming);
    cudaEventCreateWithFlags(&evj, cudaEventDisableTiming);

    const int ptile = 128 * TILES;
    int chunk = (n + NCHUNK - 1) / NCHUNK;
    chunk = (chunk + ptile - 1) / ptile * ptile;   // multiple of 512

    for (int i = 0; i < NCHUNK; i++) {
        int cbase = i * chunk;
        if (cbase >= n) break;
        int cnt = n - cbase; if (cnt > chunk) cnt = chunk;
        encode_kernel<<<(cnt + 255) / 256, 256>>>(X, tab, W1, W2, W3, W4, cbase, n);
        cudaEventRecord(evc[i], 0);
        cudaStreamWaitEvent(s2, evc[i], 0);
        mlp_kernel<<<(cnt + ptile - 1) / ptile, 128, 0, s2>>>(b1, b2, b3, b4, out, cbase, n);
    }
    // join the forked stream back into the default (captured) stream
    cudaEventRecord(evj, s2);
    cudaStreamWaitEvent(0, evj, 0);
}

// round 13
// speedup vs baseline: 1.1070x; 1.1070x over previous
#include <cuda_runtime.h>
#include <cuda_fp16.h>
#include <cstdint>

// hashNerf on sm_103 (plain target), R13: two-chunk two-stream pipeline,
// wave-quantization fixed (MLP grid per chunk = 2048 CTAs = 4.6 waves).
// encode chunk i (stream 0) --event--> mlp chunk i (stream s2);
// mlp0 overlaps encode1. Kernels are the proven R8 forms.

#define LVL   16
#define TSZ   262144
#define TMASK 0x3FFFFu
#define N_PTS_MAX 1048576
#define TILES 2
#define NCHUNK 2
#define N_TAB {16.f,21.f,27.f,36.f,48.f,64.f,84.f,111.f,147.f,194.f,256.f,337.f,445.f,588.f,776.f,1024.f}

#define WPAD 72          // weight row stride in halves (144B -> conflict-free ldmatrix)
#define FPAD 40          // feature row stride in halves (80B, 16B-aligned rows)
#define OFF_W1 0
#define OFF_W2 2304      // 32*72
#define OFF_W3 6912      // 2304 + 64*72
#define OFF_W4 11520     // 6912 + 64*72
#define IMG_HALVES 12032 // + 64*8
#define PREP_BLOCKS 47   // ceil(12032/256)

__device__ __align__(16) unsigned short g_prepW[IMG_HALVES];
__device__ uint4 g_feat[N_PTS_MAX * 4];   // 32 f16 per point = 4 uint4

// ---------- helpers ----------
__device__ __forceinline__ uint32_t smem_u32(const void* p) {
    uint32_t a;
    asm("{ .reg .u64 t; cvta.to.shared.u64 t, %1; cvt.u32.u64 %0, t; }" : "=r"(a) : "l"(p));
    return a;
}
__device__ __forceinline__ uint32_t pack_h2(float lo, float hi) {
    uint32_t r;
    asm("cvt.rn.f16x2.f32 %0, %1, %2;" : "=r"(r) : "f"(hi), "f"(lo));
    return r;
}
__device__ __forceinline__ void ldsm_x4(uint32_t& r0, uint32_t& r1, uint32_t& r2, uint32_t& r3, uint32_t addr) {
    asm volatile("ldmatrix.sync.aligned.m8n8.x4.shared.b16 {%0,%1,%2,%3}, [%4];"
                 : "=r"(r0), "=r"(r1), "=r"(r2), "=r"(r3) : "r"(addr));
}
__device__ __forceinline__ void ldsm_x4_t(uint32_t& r0, uint32_t& r1, uint32_t& r2, uint32_t& r3, uint32_t addr) {
    asm volatile("ldmatrix.sync.aligned.m8n8.x4.trans.shared.b16 {%0,%1,%2,%3}, [%4];"
                 : "=r"(r0), "=r"(r1), "=r"(r2), "=r"(r3) : "r"(addr));
}
__device__ __forceinline__ void ldsm_x2_t(uint32_t& r0, uint32_t& r1, uint32_t addr) {
    asm volatile("ldmatrix.sync.aligned.m8n8.x2.trans.shared.b16 {%0,%1}, [%2];"
                 : "=r"(r0), "=r"(r1) : "r"(addr));
}
__device__ __forceinline__ void mma16816(float* c, const uint32_t* a, uint32_t b0, uint32_t b1) {
    asm volatile("mma.sync.aligned.m16n8k16.row.col.f32.f16.f16.f32 "
                 "{%0,%1,%2,%3}, {%4,%5,%6,%7}, {%8,%9}, {%0,%1,%2,%3};"
                 : "+f"(c[0]), "+f"(c[1]), "+f"(c[2]), "+f"(c[3])
                 : "r"(a[0]), "r"(a[1]), "r"(a[2]), "r"(a[3]), "r"(b0), "r"(b1));
}
__device__ __forceinline__ float lrelu(float v) { return (v >= 0.f) ? v : 0.01f * v; }

// ---------- K1: hash encode (+ inline weight prep on first 47 blocks of chunk 0) ----------
__global__ void __launch_bounds__(256)
encode_kernel(const float* __restrict__ X, const float* __restrict__ tab,
              const float* __restrict__ W1, const float* __restrict__ W2,
              const float* __restrict__ W3, const float* __restrict__ W4,
              int base, int n) {
    const int tid = threadIdx.x;

    if (base == 0 && blockIdx.x < PREP_BLOCKS) {
        int idx = blockIdx.x * 256 + tid;
        if (idx < IMG_HALVES) {
            float v = 0.f;
            if (idx < OFF_W2) {
                int k = idx / WPAD, c = idx % WPAD;
                if (c < 64) v = W1[k * 64 + c];
            } else if (idx < OFF_W3) {
                int j = idx - OFF_W2, k = j / WPAD, c = j % WPAD;
                if (c < 64) v = W2[k * 64 + c];
            } else if (idx < OFF_W4) {
                int j = idx - OFF_W3, k = j / WPAD, c = j % WPAD;
                if (c < 64) v = W3[k * 64 + c];
            } else {
                int j = idx - OFF_W4, k = j >> 3, c = j & 7;
                if (c < 3) v = W4[k * 3 + c];
            }
            unsigned short hv;
            asm("{ .reg .b16 t; cvt.rn.f16.f32 t, %1; mov.b16 %0, t; }" : "=h"(hv) : "f"(v));
            g_prepW[idx] = hv;
        }
    }

    const int pt = base + blockIdx.x * 256 + tid;
    if (pt >= n) return;
    const float Ntab[16] = N_TAB;
    const float2 xy = __ldg((const float2*)X + pt);
    const float x = xy.x, y = xy.y;

    uint32_t packed[16];
#pragma unroll
    for (int l = 0; l < LVL; l++) {
        float xs = x * Ntab[l], ys = y * Ntab[l];
        float xf = floorf(xs), yf = floorf(ys);
        unsigned xi = (unsigned)xf, yi = (unsigned)yf;
        unsigned hy = (yi * 2654435761u) & TMASK;
        unsigned hx = xi;                 // < 2^18 already
        unsigned hxy = hx ^ hy;
        const float2* tl = (const float2*)tab + (size_t)l * TSZ;
        float2 v0 = __ldg(tl);
        float2 v1 = __ldg(tl + hy);
        float2 v2 = __ldg(tl + hx);
        float2 v3 = __ldg(tl + hxy);
        float fx = xs - xf, fy = ys - yf;
        float cx = 1.f - fx, cy = 1.f - fy;
        float w0 = cx * cy, w1 = cx * fy, w2 = fx * cy, w3 = fx * fy;
        float f0 = w0 * v0.x + w1 * v1.x + w2 * v2.x + w3 * v3.x;
        float f1 = w0 * v0.y + w1 * v1.y + w2 * v2.y + w3 * v3.y;
        packed[l] = pack_h2(f0, f1);
    }
    uint4* dst = g_feat + (size_t)pt * 4;
#pragma unroll
    for (int i = 0; i < 4; i++)
        dst[i] = make_uint4(packed[4 * i], packed[4 * i + 1], packed[4 * i + 2], packed[4 * i + 3]);
}

// ---------- K2: MLP (32 pts/warp, R8 structure) ----------
__global__ void __launch_bounds__(128)
mlp_kernel(const float* __restrict__ b1, const float* __restrict__ b2,
           const float* __restrict__ b3, const float* __restrict__ b4,
           float* __restrict__ out, int base, int n) {
    __shared__ __align__(16) unsigned short sW[IMG_HALVES];      // 24064 B
    __shared__ __align__(16) unsigned short sF[4][32 * FPAD];    // 10240 B
    __shared__ float sb[3][64];
    __shared__ float sb4[8];

    const int tid  = threadIdx.x;
    const int warp = tid >> 5;
    const int lane = tid & 31;

    {
        const uint4* src = (const uint4*)g_prepW;
        uint4* dst = (uint4*)sW;
        for (int i = tid; i < IMG_HALVES / 8; i += 128) dst[i] = src[i];
    }
    if (tid < 64) { sb[0][tid] = b1[tid]; sb[1][tid] = b2[tid]; sb[2][tid] = b3[tid]; }
    if (tid < 8) sb4[tid] = (tid < 3) ? b4[tid] : 0.f;
    __syncthreads();

    const uint32_t uW = smem_u32(sW);
    const uint32_t uF = smem_u32(sF[warp]);
    const int l15 = lane & 15;
    const int lhi = (lane >> 4) << 3;       // +8 halves for upper half-warp
    const int tg2 = (lane & 3) << 1;        // accumulator column pair base
    const int g   = lane >> 2;              // accumulator row base

#pragma unroll 1
    for (int it = 0; it < TILES; it++) {
        const int pbase = base + (blockIdx.x * TILES + it) * 128 + warp * 32;
        if (pbase >= n) break;

        // stage this warp's 32 feature rows (coalesced uint4 copy into FPAD rows)
        __syncwarp();   // it>0: prior ldsm reads complete before overwrite
        {
            const uint4* src = g_feat + (size_t)pbase * 4;   // 128 uint4
            unsigned short* dstbase = sF[warp];
#pragma unroll
            for (int i = 0; i < 4; i++) {
                int j = lane + 32 * i;                        // 0..127
                uint4 v = src[j];                             // point j>>2, slot j&3
                *(uint4*)(dstbase + (j >> 2) * FPAD + (j & 3) * 8) = v;
            }
        }
        __syncwarp();

        // A fragments: a[mtile][ktile][4]
        uint32_t a[2][4][4];
#pragma unroll
        for (int mt = 0; mt < 2; mt++)
#pragma unroll
            for (int kt = 0; kt < 2; kt++) {
                uint32_t ad = uF + (uint32_t)(((mt * 16 + l15) * FPAD + kt * 16 + lhi) * 2);
                ldsm_x4(a[mt][kt][0], a[mt][kt][1], a[mt][kt][2], a[mt][kt][3], ad);
            }

        const uint32_t woffs[3] = {OFF_W1 * 2u, OFF_W2 * 2u, OFF_W3 * 2u};
        const int nkts[3] = {2, 4, 4};

#pragma unroll 1
        for (int layer = 0; layer < 3; layer++) {
            const uint32_t wb = uW + woffs[layer];
            const int nkt = nkts[layer];
            float c[2][8][4];
#pragma unroll
            for (int mt = 0; mt < 2; mt++)
#pragma unroll
                for (int nt = 0; nt < 8; nt++) {
                    float v0 = sb[layer][8 * nt + tg2];
                    float v1 = sb[layer][8 * nt + tg2 + 1];
                    c[mt][nt][0] = v0; c[mt][nt][1] = v1;
                    c[mt][nt][2] = v0; c[mt][nt][3] = v1;
                }
#pragma unroll
            for (int kt = 0; kt < 4; kt++) {
                if (kt >= nkt) break;
#pragma unroll
                for (int n2 = 0; n2 < 4; n2++) {
                    uint32_t b0, b1, b2, b3;
                    uint32_t bd = wb + (uint32_t)(((kt * 16 + l15) * WPAD + n2 * 16 + lhi) * 2);
                    ldsm_x4_t(b0, b1, b2, b3, bd);
#pragma unroll
                    for (int mt = 0; mt < 2; mt++) {
                        mma16816(c[mt][2 * n2],     a[mt][kt], b0, b1);
                        mma16816(c[mt][2 * n2 + 1], a[mt][kt], b2, b3);
                    }
                }
            }
            // leaky-relu + repack accumulators as next-layer A fragments
#pragma unroll
            for (int mt = 0; mt < 2; mt++)
#pragma unroll
                for (int j = 0; j < 4; j++) {
                    a[mt][j][0] = pack_h2(lrelu(c[mt][2 * j][0]),     lrelu(c[mt][2 * j][1]));
                    a[mt][j][1] = pack_h2(lrelu(c[mt][2 * j][2]),     lrelu(c[mt][2 * j][3]));
                    a[mt][j][2] = pack_h2(lrelu(c[mt][2 * j + 1][0]), lrelu(c[mt][2 * j + 1][1]));
                    a[mt][j][3] = pack_h2(lrelu(c[mt][2 * j + 1][2]), lrelu(c[mt][2 * j + 1][3]));
                }
        }

        // ---- layer 4: 64 -> 3 (single n8 tile, cols 3..7 zero-padded) ----
        float c4[2][4];
#pragma unroll
        for (int mt = 0; mt < 2; mt++) {
            c4[mt][0] = sb4[tg2]; c4[mt][1] = sb4[tg2 + 1];
            c4[mt][2] = sb4[tg2]; c4[mt][3] = sb4[tg2 + 1];
        }
#pragma unroll
        for (int kt = 0; kt < 4; kt++) {
            uint32_t b0, b1;
            uint32_t bd = uW + OFF_W4 * 2u + (uint32_t)(((kt * 16 + l15) * 8) * 2);
            ldsm_x2_t(b0, b1, bd);
#pragma unroll
            for (int mt = 0; mt < 2; mt++) mma16816(c4[mt], a[mt][kt], b0, b1);
        }

        // relu + predicated stores: rows (g, g+8) per m-tile, cols (tg2, tg2+1)
#pragma unroll
        for (int mt = 0; mt < 2; mt++) {
            int p0 = pbase + mt * 16 + g;
            int p1 = p0 + 8;
            float v0 = fmaxf(c4[mt][0], 0.f), v1 = fmaxf(c4[mt][1], 0.f);
            float v2 = fmaxf(c4[mt][2], 0.f), v3 = fmaxf(c4[mt][3], 0.f);
            if (tg2 < 3) {
                if (p0 < n) out[3 * p0 + tg2] = v0;
                if (p1 < n) out[3 * p1 + tg2] = v2;
            }
            if (tg2 + 1 < 3) {
                if (p0 < n) out[3 * p0 + tg2 + 1] = v1;
                if (p1 < n) out[3 * p1 + tg2 + 1] = v3;
            }
        }
    }
}

extern "C" void kernel_launch(void* const* d_in, const int* in_sizes, int n_in,
                              void* d_out, int out_size) {
    const float* X   = (const float*)d_in[0];
    const float* tab = (const float*)d_in[1];
    const float* W1  = (const float*)d_in[2];
    const float* b1  = (const float*)d_in[3];
    const float* W2  = (const float*)d_in[4];
    const float* b2  = (const float*)d_in[5];
    const float* W3  = (const float*)d_in[6];
    const float* b3  = (const float*)d_in[7];
    const float* W4  = (const float*)d_in[8];
    const float* b4  = (const float*)d_in[9];
    float* out = (float*)d_out;

    int n = in_sizes[0] / 2;

    // Fork a second stream inside the (captured) default stream.
    // Host-side handles only (no device memory).
    cudaStream_t s2;
    cudaStreamCreateWithFlags(&s2, cudaStreamNonBlocking);
    cudaEvent_t evc[NCHUNK], evj;
    for (int i = 0; i < NCHUNK; i++) cudaEventCreateWithFlags(&evc[i], cudaEventDisableTiming);
    cudaEventCreateWithFlags(&evj, cudaEventDisableTiming);

    const int ptile = 128 * TILES;   // 256
    int chunk = (n + NCHUNK - 1) / NCHUNK;
    chunk = (chunk + ptile - 1) / ptile * ptile;

    for (int i = 0; i < NCHUNK; i++) {
        int cbase = i * chunk;
        if (cbase >= n) break;
        int cnt = n - cbase; if (cnt > chunk) cnt = chunk;
        encode_kernel<<<(cnt + 255) / 256, 256>>>(X, tab, W1, W2, W3, W4, cbase, n);
        cudaEventRecord(evc[i], 0);
        cudaStreamWaitEvent(s2, evc[i], 0);
        mlp_kernel<<<(cnt + ptile - 1) / ptile, 128, 0, s2>>>(b1, b2, b3, b4, out, cbase, n);
    }
    cudaEventRecord(evj, s2);
    cudaStreamWaitEvent(0, evj, 0);
}

// round 14
// speedup vs baseline: 1.1932x; 1.0779x over previous
#include <cuda_runtime.h>
#include <cuda_fp16.h>
#include <cstdint>

// hashNerf on sm_103 (plain target), R14: consolidation of proven config.
// Serial: encode (direct __ldg gathers + inline weight prep) -> MLP
// (mma.sync m16n8k16, 32 pts/warp, TILES=4, natural regs).

#define LVL   16
#define TSZ   262144
#define TMASK 0x3FFFFu
#define N_PTS_MAX 1048576
#define TILES 4
#define N_TAB {16.f,21.f,27.f,36.f,48.f,64.f,84.f,111.f,147.f,194.f,256.f,337.f,445.f,588.f,776.f,1024.f}

#define WPAD 72          // weight row stride in halves (144B -> conflict-free ldmatrix)
#define FPAD 40          // feature row stride in halves (80B, 16B-aligned rows)
#define OFF_W1 0
#define OFF_W2 2304      // 32*72
#define OFF_W3 6912      // 2304 + 64*72
#define OFF_W4 11520     // 6912 + 64*72
#define IMG_HALVES 12032 // + 64*8
#define PREP_BLOCKS 47   // ceil(12032/256)

__device__ __align__(16) unsigned short g_prepW[IMG_HALVES];
__device__ uint4 g_feat[N_PTS_MAX * 4];   // 32 f16 per point = 4 uint4

// ---------- helpers ----------
__device__ __forceinline__ uint32_t smem_u32(const void* p) {
    uint32_t a;
    asm("{ .reg .u64 t; cvta.to.shared.u64 t, %1; cvt.u32.u64 %0, t; }" : "=r"(a) : "l"(p));
    return a;
}
__device__ __forceinline__ uint32_t pack_h2(float lo, float hi) {
    uint32_t r;
    asm("cvt.rn.f16x2.f32 %0, %1, %2;" : "=r"(r) : "f"(hi), "f"(lo));
    return r;
}
__device__ __forceinline__ void ldsm_x4(uint32_t& r0, uint32_t& r1, uint32_t& r2, uint32_t& r3, uint32_t addr) {
    asm volatile("ldmatrix.sync.aligned.m8n8.x4.shared.b16 {%0,%1,%2,%3}, [%4];"
                 : "=r"(r0), "=r"(r1), "=r"(r2), "=r"(r3) : "r"(addr));
}
__device__ __forceinline__ void ldsm_x4_t(uint32_t& r0, uint32_t& r1, uint32_t& r2, uint32_t& r3, uint32_t addr) {
    asm volatile("ldmatrix.sync.aligned.m8n8.x4.trans.shared.b16 {%0,%1,%2,%3}, [%4];"
                 : "=r"(r0), "=r"(r1), "=r"(r2), "=r"(r3) : "r"(addr));
}
__device__ __forceinline__ void ldsm_x2_t(uint32_t& r0, uint32_t& r1, uint32_t addr) {
    asm volatile("ldmatrix.sync.aligned.m8n8.x2.trans.shared.b16 {%0,%1}, [%2];"
                 : "=r"(r0), "=r"(r1) : "r"(addr));
}
__device__ __forceinline__ void mma16816(float* c, const uint32_t* a, uint32_t b0, uint32_t b1) {
    asm volatile("mma.sync.aligned.m16n8k16.row.col.f32.f16.f16.f32 "
                 "{%0,%1,%2,%3}, {%4,%5,%6,%7}, {%8,%9}, {%0,%1,%2,%3};"
                 : "+f"(c[0]), "+f"(c[1]), "+f"(c[2]), "+f"(c[3])
                 : "r"(a[0]), "r"(a[1]), "r"(a[2]), "r"(a[3]), "r"(b0), "r"(b1));
}
__device__ __forceinline__ float lrelu(float v) { return (v >= 0.f) ? v : 0.01f * v; }

// ---------- K1: hash encode (+ inline weight prep on first 47 blocks) ----------
__global__ void __launch_bounds__(256)
encode_kernel(const float* __restrict__ X, const float* __restrict__ tab,
              const float* __restrict__ W1, const float* __restrict__ W2,
              const float* __restrict__ W3, const float* __restrict__ W4, int n) {
    const int tid = threadIdx.x;

    if (blockIdx.x < PREP_BLOCKS) {
        int idx = blockIdx.x * 256 + tid;
        if (idx < IMG_HALVES) {
            float v = 0.f;
            if (idx < OFF_W2) {
                int k = idx / WPAD, c = idx % WPAD;
                if (c < 64) v = W1[k * 64 + c];
            } else if (idx < OFF_W3) {
                int j = idx - OFF_W2, k = j / WPAD, c = j % WPAD;
                if (c < 64) v = W2[k * 64 + c];
            } else if (idx < OFF_W4) {
                int j = idx - OFF_W3, k = j / WPAD, c = j % WPAD;
                if (c < 64) v = W3[k * 64 + c];
            } else {
                int j = idx - OFF_W4, k = j >> 3, c = j & 7;
                if (c < 3) v = W4[k * 3 + c];
            }
            unsigned short hv;
            asm("{ .reg .b16 t; cvt.rn.f16.f32 t, %1; mov.b16 %0, t; }" : "=h"(hv) : "f"(v));
            g_prepW[idx] = hv;
        }
    }

    const int pt = blockIdx.x * 256 + tid;
    if (pt >= n) return;
    const float Ntab[16] = N_TAB;
    const float2 xy = __ldg((const float2*)X + pt);
    const float x = xy.x, y = xy.y;

    uint32_t packed[16];
#pragma unroll
    for (int l = 0; l < LVL; l++) {
        float xs = x * Ntab[l], ys = y * Ntab[l];
        float xf = floorf(xs), yf = floorf(ys);
        unsigned xi = (unsigned)xf, yi = (unsigned)yf;
        unsigned hy = (yi * 2654435761u) & TMASK;
        unsigned hx = xi;                 // < 2^18 already
        unsigned hxy = hx ^ hy;
        const float2* tl = (const float2*)tab + (size_t)l * TSZ;
        float2 v0 = __ldg(tl);
        float2 v1 = __ldg(tl + hy);
        float2 v2 = __ldg(tl + hx);
        float2 v3 = __ldg(tl + hxy);
        float fx = xs - xf, fy = ys - yf;
        float cx = 1.f - fx, cy = 1.f - fy;
        float w0 = cx * cy, w1 = cx * fy, w2 = fx * cy, w3 = fx * fy;
        float f0 = w0 * v0.x + w1 * v1.x + w2 * v2.x + w3 * v3.x;
        float f1 = w0 * v0.y + w1 * v1.y + w2 * v2.y + w3 * v3.y;
        packed[l] = pack_h2(f0, f1);
    }
    uint4* dst = g_feat + (size_t)pt * 4;
#pragma unroll
    for (int i = 0; i < 4; i++)
        dst[i] = make_uint4(packed[4 * i], packed[4 * i + 1], packed[4 * i + 2], packed[4 * i + 3]);
}

// ---------- K2: MLP (32 pts/warp, natural regs) ----------
__global__ void __launch_bounds__(128)
mlp_kernel(const float* __restrict__ b1, const float* __restrict__ b2,
           const float* __restrict__ b3, const float* __restrict__ b4,
           float* __restrict__ out, int n) {
    __shared__ __align__(16) unsigned short sW[IMG_HALVES];      // 24064 B
    __shared__ __align__(16) unsigned short sF[4][32 * FPAD];    // 10240 B
    __shared__ float sb[3][64];
    __shared__ float sb4[8];

    const int tid  = threadIdx.x;
    const int warp = tid >> 5;
    const int lane = tid & 31;

    {
        const uint4* src = (const uint4*)g_prepW;
        uint4* dst = (uint4*)sW;
        for (int i = tid; i < IMG_HALVES / 8; i += 128) dst[i] = src[i];
    }
    if (tid < 64) { sb[0][tid] = b1[tid]; sb[1][tid] = b2[tid]; sb[2][tid] = b3[tid]; }
    if (tid < 8) sb4[tid] = (tid < 3) ? b4[tid] : 0.f;
    __syncthreads();

    const uint32_t uW = smem_u32(sW);
    const uint32_t uF = smem_u32(sF[warp]);
    const int l15 = lane & 15;
    const int lhi = (lane >> 4) << 3;       // +8 halves for upper half-warp
    const int tg2 = (lane & 3) << 1;        // accumulator column pair base
    const int g   = lane >> 2;              // accumulator row base

#pragma unroll 1
    for (int it = 0; it < TILES; it++) {
        const int pbase = (blockIdx.x * TILES + it) * 128 + warp * 32;
        if (pbase >= n) break;

        // stage this warp's 32 feature rows (coalesced uint4 copy into FPAD rows)
        __syncwarp();   // it>0: prior ldsm reads complete before overwrite
        {
            const uint4* src = g_feat + (size_t)pbase * 4;   // 128 uint4
            unsigned short* dstbase = sF[warp];
#pragma unroll
            for (int i = 0; i < 4; i++) {
                int j = lane + 32 * i;                        // 0..127
                uint4 v = src[j];                             // point j>>2, slot j&3
                *(uint4*)(dstbase + (j >> 2) * FPAD + (j & 3) * 8) = v;
            }
        }
        __syncwarp();

        // A fragments: a[mtile][ktile][4]
        uint32_t a[2][4][4];
#pragma unroll
        for (int mt = 0; mt < 2; mt++)
#pragma unroll
            for (int kt = 0; kt < 2; kt++) {
                uint32_t ad = uF + (uint32_t)(((mt * 16 + l15) * FPAD + kt * 16 + lhi) * 2);
                ldsm_x4(a[mt][kt][0], a[mt][kt][1], a[mt][kt][2], a[mt][kt][3], ad);
            }

        const uint32_t woffs[3] = {OFF_W1 * 2u, OFF_W2 * 2u, OFF_W3 * 2u};
        const int nkts[3] = {2, 4, 4};

#pragma unroll 1
        for (int layer = 0; layer < 3; layer++) {
            const uint32_t wb = uW + woffs[layer];
            const int nkt = nkts[layer];
            float c[2][8][4];
#pragma unroll
            for (int mt = 0; mt < 2; mt++)
#pragma unroll
                for (int nt = 0; nt < 8; nt++) {
                    float v0 = sb[layer][8 * nt + tg2];
                    float v1 = sb[layer][8 * nt + tg2 + 1];
                    c[mt][nt][0] = v0; c[mt][nt][1] = v1;
                    c[mt][nt][2] = v0; c[mt][nt][3] = v1;
                }
#pragma unroll
            for (int kt = 0; kt < 4; kt++) {
                if (kt >= nkt) break;
#pragma unroll
                for (int n2 = 0; n2 < 4; n2++) {
                    uint32_t b0, b1, b2, b3;
                    uint32_t bd = wb + (uint32_t)(((kt * 16 + l15) * WPAD + n2 * 16 + lhi) * 2);
                    ldsm_x4_t(b0, b1, b2, b3, bd);
#pragma unroll
                    for (int mt = 0; mt < 2; mt++) {
                        mma16816(c[mt][2 * n2],     a[mt][kt], b0, b1);
                        mma16816(c[mt][2 * n2 + 1], a[mt][kt], b2, b3);
                    }
                }
            }
            // leaky-relu + repack accumulators as next-layer A fragments
#pragma unroll
            for (int mt = 0; mt < 2; mt++)
#pragma unroll
                for (int j = 0; j < 4; j++) {
                    a[mt][j][0] = pack_h2(lrelu(c[mt][2 * j][0]),     lrelu(c[mt][2 * j][1]));
                    a[mt][j][1] = pack_h2(lrelu(c[mt][2 * j][2]),     lrelu(c[mt][2 * j][3]));
                    a[mt][j][2] = pack_h2(lrelu(c[mt][2 * j + 1][0]), lrelu(c[mt][2 * j + 1][1]));
                    a[mt][j][3] = pack_h2(lrelu(c[mt][2 * j + 1][2]), lrelu(c[mt][2 * j + 1][3]));
                }
        }

        // ---- layer 4: 64 -> 3 (single n8 tile, cols 3..7 zero-padded) ----
        float c4[2][4];
#pragma unroll
        for (int mt = 0; mt < 2; mt++) {
            c4[mt][0] = sb4[tg2]; c4[mt][1] = sb4[tg2 + 1];
            c4[mt][2] = sb4[tg2]; c4[mt][3] = sb4[tg2 + 1];
        }
#pragma unroll
        for (int kt = 0; kt < 4; kt++) {
            uint32_t b0, b1;
            uint32_t bd = uW + OFF_W4 * 2u + (uint32_t)(((kt * 16 + l15) * 8) * 2);
            ldsm_x2_t(b0, b1, bd);
#pragma unroll
            for (int mt = 0; mt < 2; mt++) mma16816(c4[mt], a[mt][kt], b0, b1);
        }

        // relu + predicated stores: rows (g, g+8) per m-tile, cols (tg2, tg2+1)
#pragma unroll
        for (int mt = 0; mt < 2; mt++) {
            int p0 = pbase + mt * 16 + g;
            int p1 = p0 + 8;
            float v0 = fmaxf(c4[mt][0], 0.f), v1 = fmaxf(c4[mt][1], 0.f);
            float v2 = fmaxf(c4[mt][2], 0.f), v3 = fmaxf(c4[mt][3], 0.f);
            if (tg2 < 3) {
                if (p0 < n) out[3 * p0 + tg2] = v0;
                if (p1 < n) out[3 * p1 + tg2] = v2;
            }
            if (tg2 + 1 < 3) {
                if (p0 < n) out[3 * p0 + tg2 + 1] = v1;
                if (p1 < n) out[3 * p1 + tg2 + 1] = v3;
            }
        }
    }
}

extern "C" void kernel_launch(void* const* d_in, const int* in_sizes, int n_in,
                              void* d_out, int out_size) {
    const float* X   = (const float*)d_in[0];
    const float* tab = (const float*)d_in[1];
    const float* W1  = (const float*)d_in[2];
    const float* b1  = (const float*)d_in[3];
    const float* W2  = (const float*)d_in[4];
    const float* b2  = (const float*)d_in[5];
    const float* W3  = (const float*)d_in[6];
    const float* b3  = (const float*)d_in[7];
    const float* W4  = (const float*)d_in[8];
    const float* b4  = (const float*)d_in[9];
    float* out = (float*)d_out;

    int n = in_sizes[0] / 2;
    encode_kernel<<<(n + 255) / 256, 256>>>(X, tab, W1, W2, W3, W4, n);
    int ptile = 128 * TILES;
    mlp_kernel<<<(n + ptile - 1) / ptile, 128>>>(b1, b2, b3, b4, out, n);
}

// round 15
// speedup vs baseline: 1.2241x; 1.0259x over previous
#include <cuda_runtime.h>
#include <cuda_fp16.h>
#include <cstdint>

// hashNerf on sm_103 (plain target), R15.
// = R14 (proven config) + pack-first f16x2 packed leaky-relu epilogue in MLP
//   (cuts ~290 issued instructions per warp-tile from the issue-bound MLP).

#define LVL   16
#define TSZ   262144
#define TMASK 0x3FFFFu
#define N_PTS_MAX 1048576
#define TILES 4
#define N_TAB {16.f,21.f,27.f,36.f,48.f,64.f,84.f,111.f,147.f,194.f,256.f,337.f,445.f,588.f,776.f,1024.f}

#define WPAD 72          // weight row stride in halves (144B -> conflict-free ldmatrix)
#define FPAD 40          // feature row stride in halves (80B, 16B-aligned rows)
#define OFF_W1 0
#define OFF_W2 2304      // 32*72
#define OFF_W3 6912      // 2304 + 64*72
#define OFF_W4 11520     // 6912 + 64*72
#define IMG_HALVES 12032 // + 64*8
#define PREP_BLOCKS 47   // ceil(12032/256)

__device__ __align__(16) unsigned short g_prepW[IMG_HALVES];
__device__ uint4 g_feat[N_PTS_MAX * 4];   // 32 f16 per point = 4 uint4

// ---------- helpers ----------
__device__ __forceinline__ uint32_t smem_u32(const void* p) {
    uint32_t a;
    asm("{ .reg .u64 t; cvta.to.shared.u64 t, %1; cvt.u32.u64 %0, t; }" : "=r"(a) : "l"(p));
    return a;
}
__device__ __forceinline__ uint32_t pack_h2(float lo, float hi) {
    uint32_t r;
    asm("cvt.rn.f16x2.f32 %0, %1, %2;" : "=r"(r) : "f"(hi), "f"(lo));
    return r;
}
// packed leaky-relu: max(v, 0.01*v) elementwise on f16x2
__device__ __forceinline__ uint32_t lrelu2(uint32_t v, uint32_t c001) {
    uint32_t s, r;
    asm("mul.f16x2 %0, %1, %2;" : "=r"(s) : "r"(v), "r"(c001));
    asm("max.f16x2 %0, %1, %2;" : "=r"(r) : "r"(v), "r"(s));
    return r;
}
__device__ __forceinline__ void ldsm_x4(uint32_t& r0, uint32_t& r1, uint32_t& r2, uint32_t& r3, uint32_t addr) {
    asm volatile("ldmatrix.sync.aligned.m8n8.x4.shared.b16 {%0,%1,%2,%3}, [%4];"
                 : "=r"(r0), "=r"(r1), "=r"(r2), "=r"(r3) : "r"(addr));
}
__device__ __forceinline__ void ldsm_x4_t(uint32_t& r0, uint32_t& r1, uint32_t& r2, uint32_t& r3, uint32_t addr) {
    asm volatile("ldmatrix.sync.aligned.m8n8.x4.trans.shared.b16 {%0,%1,%2,%3}, [%4];"
                 : "=r"(r0), "=r"(r1), "=r"(r2), "=r"(r3) : "r"(addr));
}
__device__ __forceinline__ void ldsm_x2_t(uint32_t& r0, uint32_t& r1, uint32_t addr) {
    asm volatile("ldmatrix.sync.aligned.m8n8.x2.trans.shared.b16 {%0,%1}, [%2];"
                 : "=r"(r0), "=r"(r1) : "r"(addr));
}
__device__ __forceinline__ void mma16816(float* c, const uint32_t* a, uint32_t b0, uint32_t b1) {
    asm volatile("mma.sync.aligned.m16n8k16.row.col.f32.f16.f16.f32 "
                 "{%0,%1,%2,%3}, {%4,%5,%6,%7}, {%8,%9}, {%0,%1,%2,%3};"
                 : "+f"(c[0]), "+f"(c[1]), "+f"(c[2]), "+f"(c[3])
                 : "r"(a[0]), "r"(a[1]), "r"(a[2]), "r"(a[3]), "r"(b0), "r"(b1));
}

// ---------- K1: hash encode (+ inline weight prep on first 47 blocks) ----------
__global__ void __launch_bounds__(256)
encode_kernel(const float* __restrict__ X, const float* __restrict__ tab,
              const float* __restrict__ W1, const float* __restrict__ W2,
              const float* __restrict__ W3, const float* __restrict__ W4, int n) {
    const int tid = threadIdx.x;

    if (blockIdx.x < PREP_BLOCKS) {
        int idx = blockIdx.x * 256 + tid;
        if (idx < IMG_HALVES) {
            float v = 0.f;
            if (idx < OFF_W2) {
                int k = idx / WPAD, c = idx % WPAD;
                if (c < 64) v = W1[k * 64 + c];
            } else if (idx < OFF_W3) {
                int j = idx - OFF_W2, k = j / WPAD, c = j % WPAD;
                if (c < 64) v = W2[k * 64 + c];
            } else if (idx < OFF_W4) {
                int j = idx - OFF_W3, k = j / WPAD, c = j % WPAD;
                if (c < 64) v = W3[k * 64 + c];
            } else {
                int j = idx - OFF_W4, k = j >> 3, c = j & 7;
                if (c < 3) v = W4[k * 3 + c];
            }
            unsigned short hv;
            asm("{ .reg .b16 t; cvt.rn.f16.f32 t, %1; mov.b16 %0, t; }" : "=h"(hv) : "f"(v));
            g_prepW[idx] = hv;
        }
    }

    const int pt = blockIdx.x * 256 + tid;
    if (pt >= n) return;
    const float Ntab[16] = N_TAB;
    const float2 xy = __ldg((const float2*)X + pt);
    const float x = xy.x, y = xy.y;

    uint32_t packed[16];
#pragma unroll
    for (int l = 0; l < LVL; l++) {
        float xs = x * Ntab[l], ys = y * Ntab[l];
        float xf = floorf(xs), yf = floorf(ys);
        unsigned xi = (unsigned)xf, yi = (unsigned)yf;
        unsigned hy = (yi * 2654435761u) & TMASK;
        unsigned hx = xi;                 // < 2^18 already
        unsigned hxy = hx ^ hy;
        const float2* tl = (const float2*)tab + (size_t)l * TSZ;
        float2 v0 = __ldg(tl);
        float2 v1 = __ldg(tl + hy);
        float2 v2 = __ldg(tl + hx);
        float2 v3 = __ldg(tl + hxy);
        float fx = xs - xf, fy = ys - yf;
        float cx = 1.f - fx, cy = 1.f - fy;
        float w0 = cx * cy, w1 = cx * fy, w2 = fx * cy, w3 = fx * fy;
        float f0 = w0 * v0.x + w1 * v1.x + w2 * v2.x + w3 * v3.x;
        float f1 = w0 * v0.y + w1 * v1.y + w2 * v2.y + w3 * v3.y;
        packed[l] = pack_h2(f0, f1);
    }
    uint4* dst = g_feat + (size_t)pt * 4;
#pragma unroll
    for (int i = 0; i < 4; i++)
        dst[i] = make_uint4(packed[4 * i], packed[4 * i + 1], packed[4 * i + 2], packed[4 * i + 3]);
}

// ---------- K2: MLP (32 pts/warp, natural regs, packed f16x2 epilogue) ----------
__global__ void __launch_bounds__(128)
mlp_kernel(const float* __restrict__ b1, const float* __restrict__ b2,
           const float* __restrict__ b3, const float* __restrict__ b4,
           float* __restrict__ out, int n) {
    __shared__ __align__(16) unsigned short sW[IMG_HALVES];      // 24064 B
    __shared__ __align__(16) unsigned short sF[4][32 * FPAD];    // 10240 B
    __shared__ float sb[3][64];
    __shared__ float sb4[8];

    const int tid  = threadIdx.x;
    const int warp = tid >> 5;
    const int lane = tid & 31;

    {
        const uint4* src = (const uint4*)g_prepW;
        uint4* dst = (uint4*)sW;
        for (int i = tid; i < IMG_HALVES / 8; i += 128) dst[i] = src[i];
    }
    if (tid < 64) { sb[0][tid] = b1[tid]; sb[1][tid] = b2[tid]; sb[2][tid] = b3[tid]; }
    if (tid < 8) sb4[tid] = (tid < 3) ? b4[tid] : 0.f;
    __syncthreads();

    const uint32_t uW = smem_u32(sW);
    const uint32_t uF = smem_u32(sF[warp]);
    const int l15 = lane & 15;
    const int lhi = (lane >> 4) << 3;       // +8 halves for upper half-warp
    const int tg2 = (lane & 3) << 1;        // accumulator column pair base
    const int g   = lane >> 2;              // accumulator row base
    const uint32_t c001 = pack_h2(0.01f, 0.01f);

#pragma unroll 1
    for (int it = 0; it < TILES; it++) {
        const int pbase = (blockIdx.x * TILES + it) * 128 + warp * 32;
        if (pbase >= n) break;

        // stage this warp's 32 feature rows (coalesced uint4 copy into FPAD rows)
        __syncwarp();   // it>0: prior ldsm reads complete before overwrite
        {
            const uint4* src = g_feat + (size_t)pbase * 4;   // 128 uint4
            unsigned short* dstbase = sF[warp];
#pragma unroll
            for (int i = 0; i < 4; i++) {
                int j = lane + 32 * i;                        // 0..127
                uint4 v = src[j];                             // point j>>2, slot j&3
                *(uint4*)(dstbase + (j >> 2) * FPAD + (j & 3) * 8) = v;
            }
        }
        __syncwarp();

        // A fragments: a[mtile][ktile][4]
        uint32_t a[2][4][4];
#pragma unroll
        for (int mt = 0; mt < 2; mt++)
#pragma unroll
            for (int kt = 0; kt < 2; kt++) {
                uint32_t ad = uF + (uint32_t)(((mt * 16 + l15) * FPAD + kt * 16 + lhi) * 2);
                ldsm_x4(a[mt][kt][0], a[mt][kt][1], a[mt][kt][2], a[mt][kt][3], ad);
            }

        const uint32_t woffs[3] = {OFF_W1 * 2u, OFF_W2 * 2u, OFF_W3 * 2u};
        const int nkts[3] = {2, 4, 4};

#pragma unroll 1
        for (int layer = 0; layer < 3; layer++) {
            const uint32_t wb = uW + woffs[layer];
            const int nkt = nkts[layer];
            float c[2][8][4];
#pragma unroll
            for (int mt = 0; mt < 2; mt++)
#pragma unroll
                for (int nt = 0; nt < 8; nt++) {
                    float v0 = sb[layer][8 * nt + tg2];
                    float v1 = sb[layer][8 * nt + tg2 + 1];
                    c[mt][nt][0] = v0; c[mt][nt][1] = v1;
                    c[mt][nt][2] = v0; c[mt][nt][3] = v1;
                }
#pragma unroll
            for (int kt = 0; kt < 4; kt++) {
                if (kt >= nkt) break;
#pragma unroll
                for (int n2 = 0; n2 < 4; n2++) {
                    uint32_t b0, b1, b2, b3;
                    uint32_t bd = wb + (uint32_t)(((kt * 16 + l15) * WPAD + n2 * 16 + lhi) * 2);
                    ldsm_x4_t(b0, b1, b2, b3, bd);
#pragma unroll
                    for (int mt = 0; mt < 2; mt++) {
                        mma16816(c[mt][2 * n2],     a[mt][kt], b0, b1);
                        mma16816(c[mt][2 * n2 + 1], a[mt][kt], b2, b3);
                    }
                }
            }
            // epilogue: pack raw accums to f16x2, then packed leaky-relu
#pragma unroll
            for (int mt = 0; mt < 2; mt++)
#pragma unroll
                for (int j = 0; j < 4; j++) {
                    a[mt][j][0] = lrelu2(pack_h2(c[mt][2 * j][0],     c[mt][2 * j][1]),     c001);
                    a[mt][j][1] = lrelu2(pack_h2(c[mt][2 * j][2],     c[mt][2 * j][3]),     c001);
                    a[mt][j][2] = lrelu2(pack_h2(c[mt][2 * j + 1][0], c[mt][2 * j + 1][1]), c001);
                    a[mt][j][3] = lrelu2(pack_h2(c[mt][2 * j + 1][2], c[mt][2 * j + 1][3]), c001);
                }
        }

        // ---- layer 4: 64 -> 3 (single n8 tile, cols 3..7 zero-padded) ----
        float c4[2][4];
#pragma unroll
        for (int mt = 0; mt < 2; mt++) {
            c4[mt][0] = sb4[tg2]; c4[mt][1] = sb4[tg2 + 1];
            c4[mt][2] = sb4[tg2]; c4[mt][3] = sb4[tg2 + 1];
        }
#pragma unroll
        for (int kt = 0; kt < 4; kt++) {
            uint32_t b0, b1;
            uint32_t bd = uW + OFF_W4 * 2u + (uint32_t)(((kt * 16 + l15) * 8) * 2);
            ldsm_x2_t(b0, b1, bd);
#pragma unroll
            for (int mt = 0; mt < 2; mt++) mma16816(c4[mt], a[mt][kt], b0, b1);
        }

        // relu + predicated stores: rows (g, g+8) per m-tile, cols (tg2, tg2+1)
#pragma unroll
        for (int mt = 0; mt < 2; mt++) {
            int p0 = pbase + mt * 16 + g;
            int p1 = p0 + 8;
            float v0 = fmaxf(c4[mt][0], 0.f), v1 = fmaxf(c4[mt][1], 0.f);
            float v2 = fmaxf(c4[mt][2], 0.f), v3 = fmaxf(c4[mt][3], 0.f);
            if (tg2 < 3) {
                if (p0 < n) out[3 * p0 + tg2] = v0;
                if (p1 < n) out[3 * p1 + tg2] = v2;
            }
            if (tg2 + 1 < 3) {
                if (p0 < n) out[3 * p0 + tg2 + 1] = v1;
                if (p1 < n) out[3 * p1 + tg2 + 1] = v3;
            }
        }
    }
}

extern "C" void kernel_launch(void* const* d_in, const int* in_sizes, int n_in,
                              void* d_out, int out_size) {
    const float* X   = (const float*)d_in[0];
    const float* tab = (const float*)d_in[1];
    const float* W1  = (const float*)d_in[2];
    const float* b1  = (const float*)d_in[3];
    const float* W2  = (const float*)d_in[4];
    const float* b2  = (const float*)d_in[5];
    const float* W3  = (const float*)d_in[6];
    const float* b3  = (const float*)d_in[7];
    const float* W4  = (const float*)d_in[8];
    const float* b4  = (const float*)d_in[9];
    float* out = (float*)d_out;

    int n = in_sizes[0] / 2;
    encode_kernel<<<(n + 255) / 256, 256>>>(X, tab, W1, W2, W3, W4, n);
    int ptile = 128 * TILES;
    mlp_kernel<<<(n + ptile - 1) / ptile, 128>>>(b1, b2, b3, b4, out, n);
}

// round 16
// speedup vs baseline: 1.3173x; 1.0761x over previous
#include <cuda_runtime.h>
#include <cuda_fp16.h>
#include <cstdint>

// hashNerf on sm_103 (plain target), R16.
// = R15 + zero-init MMA (D = A*B + {0}) and late packed-f16x2 bias add fused
//   into the leaky-relu epilogue: removes the ~200-instr/tile accumulator
//   bias-init block from the issue-bound MLP.

#define LVL   16
#define TSZ   262144
#define TMASK 0x3FFFFu
#define N_PTS_MAX 1048576
#define TILES 4
#define N_TAB {16.f,21.f,27.f,36.f,48.f,64.f,84.f,111.f,147.f,194.f,256.f,337.f,445.f,588.f,776.f,1024.f}

#define WPAD 72          // weight row stride in halves (144B -> conflict-free ldmatrix)
#define FPAD 40          // feature row stride in halves (80B, 16B-aligned rows)
#define OFF_W1 0
#define OFF_W2 2304      // 32*72
#define OFF_W3 6912      // 2304 + 64*72
#define OFF_W4 11520     // 6912 + 64*72
#define IMG_HALVES 12032 // + 64*8
#define PREP_BLOCKS 47   // ceil(12032/256)

__device__ __align__(16) unsigned short g_prepW[IMG_HALVES];
__device__ uint4 g_feat[N_PTS_MAX * 4];   // 32 f16 per point = 4 uint4

// ---------- helpers ----------
__device__ __forceinline__ uint32_t smem_u32(const void* p) {
    uint32_t a;
    asm("{ .reg .u64 t; cvta.to.shared.u64 t, %1; cvt.u32.u64 %0, t; }" : "=r"(a) : "l"(p));
    return a;
}
__device__ __forceinline__ uint32_t pack_h2(float lo, float hi) {
    uint32_t r;
    asm("cvt.rn.f16x2.f32 %0, %1, %2;" : "=r"(r) : "f"(hi), "f"(lo));
    return r;
}
__device__ __forceinline__ uint32_t add2(uint32_t x, uint32_t y) {
    uint32_t r;
    asm("add.f16x2 %0, %1, %2;" : "=r"(r) : "r"(x), "r"(y));
    return r;
}
// packed leaky-relu: max(v, 0.01*v) elementwise on f16x2
__device__ __forceinline__ uint32_t lrelu2(uint32_t v, uint32_t c001) {
    uint32_t s, r;
    asm("mul.f16x2 %0, %1, %2;" : "=r"(s) : "r"(v), "r"(c001));
    asm("max.f16x2 %0, %1, %2;" : "=r"(r) : "r"(v), "r"(s));
    return r;
}
__device__ __forceinline__ void ldsm_x4(uint32_t& r0, uint32_t& r1, uint32_t& r2, uint32_t& r3, uint32_t addr) {
    asm volatile("ldmatrix.sync.aligned.m8n8.x4.shared.b16 {%0,%1,%2,%3}, [%4];"
                 : "=r"(r0), "=r"(r1), "=r"(r2), "=r"(r3) : "r"(addr));
}
__device__ __forceinline__ void ldsm_x4_t(uint32_t& r0, uint32_t& r1, uint32_t& r2, uint32_t& r3, uint32_t addr) {
    asm volatile("ldmatrix.sync.aligned.m8n8.x4.trans.shared.b16 {%0,%1,%2,%3}, [%4];"
                 : "=r"(r0), "=r"(r1), "=r"(r2), "=r"(r3) : "r"(addr));
}
__device__ __forceinline__ void ldsm_x2_t(uint32_t& r0, uint32_t& r1, uint32_t addr) {
    asm volatile("ldmatrix.sync.aligned.m8n8.x2.trans.shared.b16 {%0,%1}, [%2];"
                 : "=r"(r0), "=r"(r1) : "r"(addr));
}
__device__ __forceinline__ void mma16816(float* c, const uint32_t* a, uint32_t b0, uint32_t b1) {
    asm volatile("mma.sync.aligned.m16n8k16.row.col.f32.f16.f16.f32 "
                 "{%0,%1,%2,%3}, {%4,%5,%6,%7}, {%8,%9}, {%0,%1,%2,%3};"
                 : "+f"(c[0]), "+f"(c[1]), "+f"(c[2]), "+f"(c[3])
                 : "r"(a[0]), "r"(a[1]), "r"(a[2]), "r"(a[3]), "r"(b0), "r"(b1));
}
// first K-step: D = A*B + 0 (no accumulator pre-init needed)
__device__ __forceinline__ void mma16816_z(float* c, const uint32_t* a, uint32_t b0, uint32_t b1) {
    asm volatile("mma.sync.aligned.m16n8k16.row.col.f32.f16.f16.f32 "
                 "{%0,%1,%2,%3}, {%4,%5,%6,%7}, {%8,%9}, {%10,%10,%10,%10};"
                 : "=f"(c[0]), "=f"(c[1]), "=f"(c[2]), "=f"(c[3])
                 : "r"(a[0]), "r"(a[1]), "r"(a[2]), "r"(a[3]), "r"(b0), "r"(b1), "f"(0.f));
}

// ---------- K1: hash encode (+ inline weight prep on first 47 blocks) ----------
__global__ void __launch_bounds__(256)
encode_kernel(const float* __restrict__ X, const float* __restrict__ tab,
              const float* __restrict__ W1, const float* __restrict__ W2,
              const float* __restrict__ W3, const float* __restrict__ W4, int n) {
    const int tid = threadIdx.x;

    if (blockIdx.x < PREP_BLOCKS) {
        int idx = blockIdx.x * 256 + tid;
        if (idx < IMG_HALVES) {
            float v = 0.f;
            if (idx < OFF_W2) {
                int k = idx / WPAD, c = idx % WPAD;
                if (c < 64) v = W1[k * 64 + c];
            } else if (idx < OFF_W3) {
                int j = idx - OFF_W2, k = j / WPAD, c = j % WPAD;
                if (c < 64) v = W2[k * 64 + c];
            } else if (idx < OFF_W4) {
                int j = idx - OFF_W3, k = j / WPAD, c = j % WPAD;
                if (c < 64) v = W3[k * 64 + c];
            } else {
                int j = idx - OFF_W4, k = j >> 3, c = j & 7;
                if (c < 3) v = W4[k * 3 + c];
            }
            unsigned short hv;
            asm("{ .reg .b16 t; cvt.rn.f16.f32 t, %1; mov.b16 %0, t; }" : "=h"(hv) : "f"(v));
            g_prepW[idx] = hv;
        }
    }

    const int pt = blockIdx.x * 256 + tid;
    if (pt >= n) return;
    const float Ntab[16] = N_TAB;
    const float2 xy = __ldg((const float2*)X + pt);
    const float x = xy.x, y = xy.y;

    uint32_t packed[16];
#pragma unroll
    for (int l = 0; l < LVL; l++) {
        float xs = x * Ntab[l], ys = y * Ntab[l];
        float xf = floorf(xs), yf = floorf(ys);
        unsigned xi = (unsigned)xf, yi = (unsigned)yf;
        unsigned hy = (yi * 2654435761u) & TMASK;
        unsigned hx = xi;                 // < 2^18 already
        unsigned hxy = hx ^ hy;
        const float2* tl = (const float2*)tab + (size_t)l * TSZ;
        float2 v0 = __ldg(tl);
        float2 v1 = __ldg(tl + hy);
        float2 v2 = __ldg(tl + hx);
        float2 v3 = __ldg(tl + hxy);
        float fx = xs - xf, fy = ys - yf;
        float cx = 1.f - fx, cy = 1.f - fy;
        float w0 = cx * cy, w1 = cx * fy, w2 = fx * cy, w3 = fx * fy;
        float f0 = w0 * v0.x + w1 * v1.x + w2 * v2.x + w3 * v3.x;
        float f1 = w0 * v0.y + w1 * v1.y + w2 * v2.y + w3 * v3.y;
        packed[l] = pack_h2(f0, f1);
    }
    uint4* dst = g_feat + (size_t)pt * 4;
#pragma unroll
    for (int i = 0; i < 4; i++)
        dst[i] = make_uint4(packed[4 * i], packed[4 * i + 1], packed[4 * i + 2], packed[4 * i + 3]);
}

// ---------- K2: MLP (32 pts/warp, zero-init MMA + late packed bias) ----------
__global__ void __launch_bounds__(128)
mlp_kernel(const float* __restrict__ b1, const float* __restrict__ b2,
           const float* __restrict__ b3, const float* __restrict__ b4,
           float* __restrict__ out, int n) {
    __shared__ __align__(16) unsigned short sW[IMG_HALVES];      // 24064 B
    __shared__ __align__(16) unsigned short sF[4][32 * FPAD];    // 10240 B
    __shared__ uint32_t sbp[3][32];   // biases packed f16x2: sbp[l][j] = (b[2j], b[2j+1])
    __shared__ float sb4[8];

    const int tid  = threadIdx.x;
    const int warp = tid >> 5;
    const int lane = tid & 31;

    {
        const uint4* src = (const uint4*)g_prepW;
        uint4* dst = (uint4*)sW;
        for (int i = tid; i < IMG_HALVES / 8; i += 128) dst[i] = src[i];
    }
    if (tid < 96) {
        const float* bsrc = (tid < 32) ? b1 : (tid < 64) ? b2 : b3;
        int j = tid & 31;
        sbp[tid >> 5][j] = pack_h2(bsrc[2 * j], bsrc[2 * j + 1]);
    }
    if (tid < 8) sb4[tid] = (tid < 3) ? b4[tid] : 0.f;
    __syncthreads();

    const uint32_t uW = smem_u32(sW);
    const uint32_t uF = smem_u32(sF[warp]);
    const int l15 = lane & 15;
    const int lhi = (lane >> 4) << 3;       // +8 halves for upper half-warp
    const int tg  = lane & 3;               // thread group within quad row
    const int tg2 = tg << 1;                // accumulator column pair base
    const int g   = lane >> 2;              // accumulator row base
    const uint32_t c001 = pack_h2(0.01f, 0.01f);

#pragma unroll 1
    for (int it = 0; it < TILES; it++) {
        const int pbase = (blockIdx.x * TILES + it) * 128 + warp * 32;
        if (pbase >= n) break;

        // stage this warp's 32 feature rows (coalesced uint4 copy into FPAD rows)
        __syncwarp();   // it>0: prior ldsm reads complete before overwrite
        {
            const uint4* src = g_feat + (size_t)pbase * 4;   // 128 uint4
            unsigned short* dstbase = sF[warp];
#pragma unroll
            for (int i = 0; i < 4; i++) {
                int j = lane + 32 * i;                        // 0..127
                uint4 v = src[j];                             // point j>>2, slot j&3
                *(uint4*)(dstbase + (j >> 2) * FPAD + (j & 3) * 8) = v;
            }
        }
        __syncwarp();

        // A fragments: a[mtile][ktile][4]
        uint32_t a[2][4][4];
#pragma unroll
        for (int mt = 0; mt < 2; mt++)
#pragma unroll
            for (int kt = 0; kt < 2; kt++) {
                uint32_t ad = uF + (uint32_t)(((mt * 16 + l15) * FPAD + kt * 16 + lhi) * 2);
                ldsm_x4(a[mt][kt][0], a[mt][kt][1], a[mt][kt][2], a[mt][kt][3], ad);
            }

        const uint32_t woffs[3] = {OFF_W1 * 2u, OFF_W2 * 2u, OFF_W3 * 2u};
        const int nkts[3] = {2, 4, 4};

#pragma unroll 1
        for (int layer = 0; layer < 3; layer++) {
            const uint32_t wb = uW + woffs[layer];
            const int nkt = nkts[layer];
            float c[2][8][4];
#pragma unroll
            for (int kt = 0; kt < 4; kt++) {
                if (kt >= nkt) break;
#pragma unroll
                for (int n2 = 0; n2 < 4; n2++) {
                    uint32_t b0, b1, b2, b3;
                    uint32_t bd = wb + (uint32_t)(((kt * 16 + l15) * WPAD + n2 * 16 + lhi) * 2);
                    ldsm_x4_t(b0, b1, b2, b3, bd);
                    if (kt == 0) {
#pragma unroll
                        for (int mt = 0; mt < 2; mt++) {
                            mma16816_z(c[mt][2 * n2],     a[mt][0], b0, b1);
                            mma16816_z(c[mt][2 * n2 + 1], a[mt][0], b2, b3);
                        }
                    } else {
#pragma unroll
                        for (int mt = 0; mt < 2; mt++) {
                            mma16816(c[mt][2 * n2],     a[mt][kt], b0, b1);
                            mma16816(c[mt][2 * n2 + 1], a[mt][kt], b2, b3);
                        }
                    }
                }
            }
            // epilogue: pack raw accums to f16x2, add packed bias, packed leaky-relu
#pragma unroll
            for (int j = 0; j < 4; j++) {
                uint32_t bA = sbp[layer][8 * j + tg];       // cols of nt=2j
                uint32_t bB = sbp[layer][8 * j + 4 + tg];   // cols of nt=2j+1
#pragma unroll
                for (int mt = 0; mt < 2; mt++) {
                    a[mt][j][0] = lrelu2(add2(pack_h2(c[mt][2 * j][0],     c[mt][2 * j][1]),     bA), c001);
                    a[mt][j][1] = lrelu2(add2(pack_h2(c[mt][2 * j][2],     c[mt][2 * j][3]),     bA), c001);
                    a[mt][j][2] = lrelu2(add2(pack_h2(c[mt][2 * j + 1][0], c[mt][2 * j + 1][1]), bB), c001);
                    a[mt][j][3] = lrelu2(add2(pack_h2(c[mt][2 * j + 1][2], c[mt][2 * j + 1][3]), bB), c001);
                }
            }
        }

        // ---- layer 4: 64 -> 3 (single n8 tile, cols 3..7 zero-padded, fp32) ----
        float c4[2][4];
#pragma unroll
        for (int mt = 0; mt < 2; mt++) {
            c4[mt][0] = sb4[tg2]; c4[mt][1] = sb4[tg2 + 1];
            c4[mt][2] = sb4[tg2]; c4[mt][3] = sb4[tg2 + 1];
        }
#pragma unroll
        for (int kt = 0; kt < 4; kt++) {
            uint32_t b0, b1;
            uint32_t bd = uW + OFF_W4 * 2u + (uint32_t)(((kt * 16 + l15) * 8) * 2);
            ldsm_x2_t(b0, b1, bd);
#pragma unroll
            for (int mt = 0; mt < 2; mt++) mma16816(c4[mt], a[mt][kt], b0, b1);
        }

        // relu + predicated stores: rows (g, g+8) per m-tile, cols (tg2, tg2+1)
#pragma unroll
        for (int mt = 0; mt < 2; mt++) {
            int p0 = pbase + mt * 16 + g;
            int p1 = p0 + 8;
            float v0 = fmaxf(c4[mt][0], 0.f), v1 = fmaxf(c4[mt][1], 0.f);
            float v2 = fmaxf(c4[mt][2], 0.f), v3 = fmaxf(c4[mt][3], 0.f);
            if (tg2 < 3) {
                if (p0 < n) out[3 * p0 + tg2] = v0;
                if (p1 < n) out[3 * p1 + tg2] = v2;
            }
            if (tg2 + 1 < 3) {
                if (p0 < n) out[3 * p0 + tg2 + 1] = v1;
                if (p1 < n) out[3 * p1 + tg2 + 1] = v3;
            }
        }
    }
}

extern "C" void kernel_launch(void* const* d_in, const int* in_sizes, int n_in,
                              void* d_out, int out_size) {
    const float* X   = (const float*)d_in[0];
    const float* tab = (const float*)d_in[1];
    const float* W1  = (const float*)d_in[2];
    const float* b1  = (const float*)d_in[3];
    const float* W2  = (const float*)d_in[4];
    const float* b2  = (const float*)d_in[5];
    const float* W3  = (const float*)d_in[6];
    const float* b3  = (const float*)d_in[7];
    const float* W4  = (const float*)d_in[8];
    const float* b4  = (const float*)d_in[9];
    float* out = (float*)d_out;

    int n = in_sizes[0] / 2;
    encode_kernel<<<(n + 255) / 256, 256>>>(X, tab, W1, W2, W3, W4, n);
    int ptile = 128 * TILES;
    mlp_kernel<<<(n + ptile - 1) / ptile, 128>>>(b1, b2, b3, b4, out, n);
}

// round 17
// speedup vs baseline: 1.3634x; 1.0350x over previous
#include <cuda_runtime.h>
#include <cuda_fp16.h>
#include <cstdint>

// hashNerf on sm_103 (plain target), R17: warp-specialized fused kernel.
// Warps 0-3 (producers): hash-encode 128 pts/tile into smem feature slots.
// Warps 4-7 (consumers): HMMA MLP (R16 body) from the other slot.
// Software-pipelined double buffer, one __syncthreads per iteration.
// No g_feat HBM round-trip; weights converted to f16 smem per CTA at init.

#define LVL   16
#define TSZ   262144
#define TMASK 0x3FFFFu
#define N_TAB {16.f,21.f,27.f,36.f,48.f,64.f,84.f,111.f,147.f,194.f,256.f,337.f,445.f,588.f,776.f,1024.f}

#define WPAD 72          // weight row stride in halves (144B -> conflict-free ldmatrix)
#define FPAD 40          // feature row stride in halves (80B, 16B-aligned rows)
#define OFF_W1 0
#define OFF_W2 2304      // 32*72
#define OFF_W3 6912      // 2304 + 64*72
#define OFF_W4 11520     // 6912 + 64*72
#define IMG_HALVES 12032 // + 64*8
#define GRIDV 296        // 2 CTAs/SM * 148 SMs

// ---------- helpers ----------
__device__ __forceinline__ uint32_t smem_u32(const void* p) {
    uint32_t a;
    asm("{ .reg .u64 t; cvta.to.shared.u64 t, %1; cvt.u32.u64 %0, t; }" : "=r"(a) : "l"(p));
    return a;
}
__device__ __forceinline__ uint32_t pack_h2(float lo, float hi) {
    uint32_t r;
    asm("cvt.rn.f16x2.f32 %0, %1, %2;" : "=r"(r) : "f"(hi), "f"(lo));
    return r;
}
__device__ __forceinline__ uint32_t add2(uint32_t x, uint32_t y) {
    uint32_t r;
    asm("add.f16x2 %0, %1, %2;" : "=r"(r) : "r"(x), "r"(y));
    return r;
}
__device__ __forceinline__ uint32_t lrelu2(uint32_t v, uint32_t c001) {
    uint32_t s, r;
    asm("mul.f16x2 %0, %1, %2;" : "=r"(s) : "r"(v), "r"(c001));
    asm("max.f16x2 %0, %1, %2;" : "=r"(r) : "r"(v), "r"(s));
    return r;
}
__device__ __forceinline__ void ldsm_x4(uint32_t& r0, uint32_t& r1, uint32_t& r2, uint32_t& r3, uint32_t addr) {
    asm volatile("ldmatrix.sync.aligned.m8n8.x4.shared.b16 {%0,%1,%2,%3}, [%4];"
                 : "=r"(r0), "=r"(r1), "=r"(r2), "=r"(r3) : "r"(addr));
}
__device__ __forceinline__ void ldsm_x4_t(uint32_t& r0, uint32_t& r1, uint32_t& r2, uint32_t& r3, uint32_t addr) {
    asm volatile("ldmatrix.sync.aligned.m8n8.x4.trans.shared.b16 {%0,%1,%2,%3}, [%4];"
                 : "=r"(r0), "=r"(r1), "=r"(r2), "=r"(r3) : "r"(addr));
}
__device__ __forceinline__ void ldsm_x2_t(uint32_t& r0, uint32_t& r1, uint32_t addr) {
    asm volatile("ldmatrix.sync.aligned.m8n8.x2.trans.shared.b16 {%0,%1}, [%2];"
                 : "=r"(r0), "=r"(r1) : "r"(addr));
}
__device__ __forceinline__ void mma16816(float* c, const uint32_t* a, uint32_t b0, uint32_t b1) {
    asm volatile("mma.sync.aligned.m16n8k16.row.col.f32.f16.f16.f32 "
                 "{%0,%1,%2,%3}, {%4,%5,%6,%7}, {%8,%9}, {%0,%1,%2,%3};"
                 : "+f"(c[0]), "+f"(c[1]), "+f"(c[2]), "+f"(c[3])
                 : "r"(a[0]), "r"(a[1]), "r"(a[2]), "r"(a[3]), "r"(b0), "r"(b1));
}
__device__ __forceinline__ void mma16816_z(float* c, const uint32_t* a, uint32_t b0, uint32_t b1) {
    asm volatile("mma.sync.aligned.m16n8k16.row.col.f32.f16.f16.f32 "
                 "{%0,%1,%2,%3}, {%4,%5,%6,%7}, {%8,%9}, {%10,%10,%10,%10};"
                 : "=f"(c[0]), "=f"(c[1]), "=f"(c[2]), "=f"(c[3])
                 : "r"(a[0]), "r"(a[1]), "r"(a[2]), "r"(a[3]), "r"(b0), "r"(b1), "f"(0.f));
}

// ---------- fused kernel ----------
__global__ void __launch_bounds__(256, 2)
fused_kernel(const float* __restrict__ X, const float* __restrict__ tab,
             const float* __restrict__ W1, const float* __restrict__ b1,
             const float* __restrict__ W2, const float* __restrict__ b2,
             const float* __restrict__ W3, const float* __restrict__ b3,
             const float* __restrict__ W4, const float* __restrict__ b4,
             float* __restrict__ out, int n) {
    __shared__ __align__(16) unsigned short sW[IMG_HALVES];          // 24064 B
    __shared__ __align__(16) unsigned short sF[2][4][32 * FPAD];     // 20480 B
    __shared__ uint32_t sbp[3][32];
    __shared__ float sb4[8];

    const int tid  = threadIdx.x;
    const int warp = tid >> 5;
    const int lane = tid & 31;

    // ---- init: convert weights fp32 -> f16 padded image in smem ----
    for (int idx = tid; idx < IMG_HALVES; idx += 256) {
        float v = 0.f;
        if (idx < OFF_W2) {
            int k = idx / WPAD, c = idx % WPAD;
            if (c < 64) v = W1[k * 64 + c];
        } else if (idx < OFF_W3) {
            int j = idx - OFF_W2, k = j / WPAD, c = j % WPAD;
            if (c < 64) v = W2[k * 64 + c];
        } else if (idx < OFF_W4) {
            int j = idx - OFF_W3, k = j / WPAD, c = j % WPAD;
            if (c < 64) v = W3[k * 64 + c];
        } else {
            int j = idx - OFF_W4, k = j >> 3, c = j & 7;
            if (c < 3) v = W4[k * 3 + c];
        }
        unsigned short hv;
        asm("{ .reg .b16 t; cvt.rn.f16.f32 t, %1; mov.b16 %0, t; }" : "=h"(hv) : "f"(v));
        sW[idx] = hv;
    }
    if (tid < 96) {
        const float* bsrc = (tid < 32) ? b1 : (tid < 64) ? b2 : b3;
        int j = tid & 31;
        sbp[tid >> 5][j] = pack_h2(bsrc[2 * j], bsrc[2 * j + 1]);
    }
    if (tid < 8) sb4[tid] = (tid < 3) ? b4[tid] : 0.f;
    __syncthreads();

    const int NT = (n + 127) >> 7;                       // 128-pt tiles
    const int iters = (NT + GRIDV - 1) / GRIDV;

    const float Ntab[16] = N_TAB;
    const uint32_t uW = smem_u32(sW);
    const int l15 = lane & 15;
    const int lhi = (lane >> 4) << 3;
    const int tg  = lane & 3;
    const int tg2 = tg << 1;
    const int g   = lane >> 2;
    const uint32_t c001 = pack_h2(0.01f, 0.01f);
    const int cw = warp - 4;                             // consumer warp 0..3

#pragma unroll 1
    for (int i = 0; i <= iters; i++) {
        if (warp < 4) {
            // ================= producer: encode tile i into slot i&1 =================
            int t = blockIdx.x + i * GRIDV;
            if (i < iters && t < NT) {
                int pt = t * 128 + tid;                  // tid 0..127
                uint32_t packed[16];
                if (pt < n) {
                    const float2 xy = __ldg((const float2*)X + pt);
                    const float x = xy.x, y = xy.y;
#pragma unroll
                    for (int l = 0; l < LVL; l++) {
                        float xs = x * Ntab[l], ys = y * Ntab[l];
                        float xf = floorf(xs), yf = floorf(ys);
                        unsigned xi = (unsigned)xf, yi = (unsigned)yf;
                        unsigned hy = (yi * 2654435761u) & TMASK;
                        unsigned hxy = xi ^ hy;
                        const float2* tl = (const float2*)tab + (size_t)l * TSZ;
                        float2 v0 = __ldg(tl);
                        float2 v1 = __ldg(tl + hy);
                        float2 v2 = __ldg(tl + xi);
                        float2 v3 = __ldg(tl + hxy);
                        float fx = xs - xf, fy = ys - yf;
                        float cx = 1.f - fx, cy = 1.f - fy;
                        float w0 = cx * cy, w1 = cx * fy, w2 = fx * cy, w3 = fx * fy;
                        float f0 = w0 * v0.x + w1 * v1.x + w2 * v2.x + w3 * v3.x;
                        float f1 = w0 * v0.y + w1 * v1.y + w2 * v2.y + w3 * v3.y;
                        packed[l] = pack_h2(f0, f1);
                    }
                } else {
#pragma unroll
                    for (int l = 0; l < LVL; l++) packed[l] = 0u;
                }
                unsigned short* dst = sF[i & 1][tid >> 5] + (tid & 31) * FPAD;
#pragma unroll
                for (int q = 0; q < 4; q++)
                    *(uint4*)(dst + q * 8) = make_uint4(packed[4 * q], packed[4 * q + 1],
                                                        packed[4 * q + 2], packed[4 * q + 3]);
            }
        } else {
            // ================= consumer: MLP tile i-1 from slot (i-1)&1 =================
            int t = blockIdx.x + (i - 1) * GRIDV;
            if (i > 0 && t < NT) {
                const int pbase = t * 128 + cw * 32;
                const uint32_t uF = smem_u32(sF[(i - 1) & 1][cw]);

                uint32_t a[2][4][4];
#pragma unroll
                for (int mt = 0; mt < 2; mt++)
#pragma unroll
                    for (int kt = 0; kt < 2; kt++) {
                        uint32_t ad = uF + (uint32_t)(((mt * 16 + l15) * FPAD + kt * 16 + lhi) * 2);
                        ldsm_x4(a[mt][kt][0], a[mt][kt][1], a[mt][kt][2], a[mt][kt][3], ad);
                    }

                const uint32_t woffs[3] = {OFF_W1 * 2u, OFF_W2 * 2u, OFF_W3 * 2u};
                const int nkts[3] = {2, 4, 4};

#pragma unroll 1
                for (int layer = 0; layer < 3; layer++) {
                    const uint32_t wb = uW + woffs[layer];
                    const int nkt = nkts[layer];
                    float c[2][8][4];
#pragma unroll
                    for (int kt = 0; kt < 4; kt++) {
                        if (kt >= nkt) break;
#pragma unroll
                        for (int n2 = 0; n2 < 4; n2++) {
                            uint32_t b0, b1r, b2r, b3r;
                            uint32_t bd = wb + (uint32_t)(((kt * 16 + l15) * WPAD + n2 * 16 + lhi) * 2);
                            ldsm_x4_t(b0, b1r, b2r, b3r, bd);
                            if (kt == 0) {
#pragma unroll
                                for (int mt = 0; mt < 2; mt++) {
                                    mma16816_z(c[mt][2 * n2],     a[mt][0], b0, b1r);
                                    mma16816_z(c[mt][2 * n2 + 1], a[mt][0], b2r, b3r);
                                }
                            } else {
#pragma unroll
                                for (int mt = 0; mt < 2; mt++) {
                                    mma16816(c[mt][2 * n2],     a[mt][kt], b0, b1r);
                                    mma16816(c[mt][2 * n2 + 1], a[mt][kt], b2r, b3r);
                                }
                            }
                        }
                    }
#pragma unroll
                    for (int j = 0; j < 4; j++) {
                        uint32_t bA = sbp[layer][8 * j + tg];
                        uint32_t bB = sbp[layer][8 * j + 4 + tg];
#pragma unroll
                        for (int mt = 0; mt < 2; mt++) {
                            a[mt][j][0] = lrelu2(add2(pack_h2(c[mt][2 * j][0],     c[mt][2 * j][1]),     bA), c001);
                            a[mt][j][1] = lrelu2(add2(pack_h2(c[mt][2 * j][2],     c[mt][2 * j][3]),     bA), c001);
                            a[mt][j][2] = lrelu2(add2(pack_h2(c[mt][2 * j + 1][0], c[mt][2 * j + 1][1]), bB), c001);
                            a[mt][j][3] = lrelu2(add2(pack_h2(c[mt][2 * j + 1][2], c[mt][2 * j + 1][3]), bB), c001);
                        }
                    }
                }

                // layer 4: 64 -> 3 (fp32)
                float c4[2][4];
#pragma unroll
                for (int mt = 0; mt < 2; mt++) {
                    c4[mt][0] = sb4[tg2]; c4[mt][1] = sb4[tg2 + 1];
                    c4[mt][2] = sb4[tg2]; c4[mt][3] = sb4[tg2 + 1];
                }
#pragma unroll
                for (int kt = 0; kt < 4; kt++) {
                    uint32_t b0, b1r;
                    uint32_t bd = uW + OFF_W4 * 2u + (uint32_t)(((kt * 16 + l15) * 8) * 2);
                    ldsm_x2_t(b0, b1r, bd);
#pragma unroll
                    for (int mt = 0; mt < 2; mt++) mma16816(c4[mt], a[mt][kt], b0, b1r);
                }

#pragma unroll
                for (int mt = 0; mt < 2; mt++) {
                    int p0 = pbase + mt * 16 + g;
                    int p1 = p0 + 8;
                    float v0 = fmaxf(c4[mt][0], 0.f), v1 = fmaxf(c4[mt][1], 0.f);
                    float v2 = fmaxf(c4[mt][2], 0.f), v3 = fmaxf(c4[mt][3], 0.f);
                    if (tg2 < 3) {
                        if (p0 < n) out[3 * p0 + tg2] = v0;
                        if (p1 < n) out[3 * p1 + tg2] = v2;
                    }
                    if (tg2 + 1 < 3) {
                        if (p0 < n) out[3 * p0 + tg2 + 1] = v1;
                        if (p1 < n) out[3 * p1 + tg2 + 1] = v3;
                    }
                }
            }
        }
        __syncthreads();
    }
}

extern "C" void kernel_launch(void* const* d_in, const int* in_sizes, int n_in,
                              void* d_out, int out_size) {
    const float* X   = (const float*)d_in[0];
    const float* tab = (const float*)d_in[1];
    const float* W1  = (const float*)d_in[2];
    const float* b1  = (const float*)d_in[3];
    const float* W2  = (const float*)d_in[4];
    const float* b2  = (const float*)d_in[5];
    const float* W3  = (const float*)d_in[6];
    const float* b3  = (const float*)d_in[7];
    const float* W4  = (const float*)d_in[8];
    const float* b4  = (const float*)d_in[9];
    float* out = (float*)d_out;

    int n = in_sizes[0] / 2;
    fused_kernel<<<GRIDV, 256>>>(X, tab, W1, b1, W2, b2, W3, b3, W4, b4, out, n);
}